// round 17
// baseline (speedup 1.0000x reference)
#include <cuda_runtime.h>
#include <cuda_bf16.h>
#include <cstdint>

// upfirdn2d: up=(2,2), down=(1,1), pad=((2,1),(2,1)), 4x4 kernel, gain*up0*up1 = 4
// x: (16, 64, 128, 128) f32  -> out: (16, 64, 255, 255) f32
//
// R16: chaining exhausted; all variants pinned at ~57.5us, L1 (64%) > DRAM
// (60%). Common cost: per-row 2-lane global edge loads (lane0 c-1 / lane31
// c+1 hit 2 different 128B lines = 2 wf each; 12 wf/strip vs 6 wf of center
// loads). This round: block spans the full 128-col row (blockDim 128x2,
// 4 warps = 4 column slabs); column halos exchanged through a 384B smem
// table + one __syncthreads -> ZERO global edge loads. Grid (1,16,1024) =
// 16384 blocks: identical parallelism/regs/stores to R12.
// Kept (validated): separable rank-1 coeffs derived in-kernel (single-node
// graph), interleaved lane->(2c,2c+1) layout, typeA dense STG.64 / typeB
// shifted-pair STG.64 (pair (j0,j0+1) 8B-aligned iff (img+i) even), .cs
// streaming stores, front-batched loads, walking pointers.

namespace {

constexpr int H = 128;
constexpr int W = 128;
constexpr int OH = 255;
constexpr int OW = 255;
constexpr int RPT = 4;             // input rows per thread strip
constexpr int NROWS = RPT + 2;     // 6
constexpr int NSLAB = 4;           // warps (column slabs) per strip

__device__ __forceinline__ void stcs2(float* p, float a, float b) {
    asm volatile("st.global.cs.v2.f32 [%0], {%1, %2};"
                 :: "l"(p), "f"(a), "f"(b) : "memory");
}
__device__ __forceinline__ void stcs1(float* p, float a) {
    asm volatile("st.global.cs.f32 [%0], %1;" :: "l"(p), "f"(a) : "memory");
}

// Store one output row's pair (a at j0, b at j0+1) for the whole warp.
// typeA: (j0,j0+1) 8B-aligned -> dense STG.64.
// typeB: (j0+1,j0+2) aligned -> lane0 scalar a; lanes<31 pair {b, a_next};
//        lane31 scalar b (j0+2 covered by the adjacent slab's lane0).
__device__ __forceinline__ void store_row(float* __restrict__ rowp /*at j0*/,
                                          float a, float b, bool typeA,
                                          bool isL, bool isR, bool tail) {
    const float an = __shfl_down_sync(0xffffffffu, a, 1);
    if (typeA) {
        if (!tail) stcs2(rowp, a, b);
        else       stcs1(rowp, a);
    } else {
        if (isL) stcs1(rowp, a);
        if (!isR)      stcs2(rowp + 1, b, an);
        else if (!tail) stcs1(rowp + 1, b);
    }
}

__global__ __launch_bounds__(256) void upfirdn_up2_kernel(
        const float* __restrict__ x, const float* __restrict__ kern,
        float* __restrict__ out) {
    const int lane  = threadIdx.x & 31;
    const int wslab = threadIdx.x >> 5;              // 0..3 (column slab)
    const int c     = threadIdx.x;                   // input col 0..127
    const int sy    = threadIdx.y;                   // strip within block
    const int strip = blockIdx.y * 2 + sy;           // 0..31
    const int r0    = strip * RPT;
    const int img   = blockIdx.z;

    const float* __restrict__ xp = x + (size_t)img * (H * W);
    float* __restrict__ op = out + (size_t)img * (OH * OW);
    const bool evenA = (img & 1) == 0;  // even output rows typeA iff img even

    // Separable coefficients: a_j = K[1][j]*rsqrt(K[1][1]); b = 2a so that
    // b (x) b = 4*K (gain folded). One broadcast LDG.128 per warp.
    float b0, b1, b2, b3;
    {
        const float4 kr = __ldg(reinterpret_cast<const float4*>(kern) + 1);
        const float s = 2.0f * rsqrtf(kr.y);
        b0 = kr.x * s; b1 = kr.y * s; b2 = kr.z * s; b3 = kr.w * s;
    }

    const bool isL = (lane == 0), isR = (lane == 31);
    const bool first = (r0 == 0), last = (r0 + RPT == H);  // warp-uniform

    // Halo exchange tables: sLv[sy][w][i] = M[i] of (slab w, lane31) -> L of
    // slab w+1; sRv[sy][w][i] = M[i] of (slab w, lane0) -> R of slab w-1.
    __shared__ float sLv[2][NSLAB][NROWS];
    __shared__ float sRv[2][NSLAB][NROWS];

    // ---- Phase 1: batch center loads (no edge loads!) ----
    float M[NROWS];
    const float* rp = xp + (ptrdiff_t)(r0 - 1) * W;
    M[0] = first ? 0.0f : rp[c];
    rp += W;
#pragma unroll
    for (int i = 1; i <= RPT; i++) { M[i] = rp[c]; rp += W; }
    M[RPT + 1] = last ? 0.0f : rp[c];

    // Publish slab edges to smem (2 lanes per warp).
    if (isL) {
#pragma unroll
        for (int i = 0; i < NROWS; i++) sRv[sy][wslab][i] = M[i];
    } else if (isR) {
#pragma unroll
        for (int i = 0; i < NROWS; i++) sLv[sy][wslab][i] = M[i];
    }
    __syncthreads();

    // ---- Phase 2: shuffles + smem halos + horizontal FIR ----
    float he[NROWS], ho[NROWS];
#pragma unroll
    for (int i = 0; i < NROWS; i++) {
        const float l = __shfl_up_sync(0xffffffffu, M[i], 1);
        const float r = __shfl_down_sync(0xffffffffu, M[i], 1);
        const float L = isL ? (wslab > 0         ? sLv[sy][wslab - 1][i] : 0.0f) : l;
        const float R = isR ? (wslab < NSLAB - 1 ? sRv[sy][wslab + 1][i] : 0.0f) : r;
        he[i] = b3 * L + b1 * M[i];    // even output column
        ho[i] = b2 * M[i] + b0 * R;    // odd output column
    }

    // ---- Phase 3: vertical FIR pass + store, walking output pointer ----
    const int j0 = 2 * c;
    const bool tail = (c == W - 1);
    float* pe = op + (size_t)(2 * r0) * OW + j0;
#pragma unroll
    for (int kk = 0; kk < RPT; kk++) {
        const float o00 = b3 * he[kk]     + b1 * he[kk + 1];
        const float o01 = b3 * ho[kk]     + b1 * ho[kk + 1];
        const float o10 = b2 * he[kk + 1] + b0 * he[kk + 2];
        const float o11 = b2 * ho[kk + 1] + b0 * ho[kk + 2];

        store_row(pe, o00, o01, evenA, isL, isR, tail);
        if (!(last && kk == RPT - 1)) {   // output row 255 is OOB
            store_row(pe + OW, o10, o11, !evenA, isL, isR, tail);
        }
        pe += 2 * OW;
    }
}

}  // namespace

extern "C" void kernel_launch(void* const* d_in, const int* in_sizes, int n_in,
                              void* d_out, int out_size) {
    const float* x = (const float*)d_in[0];      // 16*64*128*128
    const float* kern = (const float*)d_in[1];   // 4*4
    float* out = (float*)d_out;                  // 16*64*255*255

    (void)in_sizes; (void)n_in; (void)out_size;

    dim3 block(128, 2, 1);                        // 4 col-slab warps x 2 strips
    dim3 grid(1, H / (2 * RPT), 16 * 64);         // (1, 16, 1024) = 16384 blocks
    upfirdn_up2_kernel<<<grid, block>>>(x, kern, out);
}